// round 15
// baseline (speedup 1.0000x reference)
#include <cuda_runtime.h>
#include <cuda_fp16.h>
#include <math.h>
#include <stdint.h>

#define BB 8
#define NN 4096
#define KK 16
#define CC 64
#define PP (BB*NN*KK)        // 524288 positions
#define NG (PP/16)           // 32768 k-groups
#define NQ 32768             // queries (B*N)
#define C_IN 131
#define KC0 160
#define BN_EPS 1e-3f

// dynamic smem (bytes): 3 X bufs + 3 W bufs (128 rows x 80B) + scalars
#define XBUF(s) ((s)*10240)
#define WBUF(s) (30720 + (s)*10240)
#define SC_BIAS 61440
#define SC_SST  61952
#define SC_RED  62976
#define SMEM_BYTES 64000

// ---------------- scratch ----------------
__device__ int    g_idx[PP];
__device__ __align__(16) __half g_y0h[(size_t)64 * PP * 2];  // pair-interleaved [c2][pos]{2}
__device__ __align__(16) __half g_y1h[(size_t)64 * PP * 2];
__device__ float  g_ymax[(size_t)128 * NG];                  // 16MB
__device__ float  g_stats[6*128];
__device__ float  g_sst[6*128];
__device__ __align__(16) __half g_w0h[128*KC0];              // [n][k] permuted: [f2|f1|xyz|pad]
__device__ __align__(16) __half g_w1h[128*128];
__device__ __align__(16) __half g_w2h[128*128];
__device__ __align__(16) __half g_f2t[(size_t)BB*NN*64];     // [b][n][c] half, 4MB
__device__ __align__(16) __half g_f1t[(size_t)BB*NN*64];

__device__ __forceinline__ uint32_t smem_u32(const void* p) {
    uint32_t a;
    asm("{ .reg .u64 t; cvta.to.shared.u64 t, %1; cvt.u32.u64 %0, t; }" : "=r"(a) : "l"(p));
    return a;
}
__device__ __forceinline__ void cp16(uint32_t dst, const void* src) {
    asm volatile("cp.async.ca.shared.global [%0], [%1], 16;" :: "r"(dst), "l"(src));
}
__device__ __forceinline__ void cp_commit() { asm volatile("cp.async.commit_group;"); }
template<int N> __device__ __forceinline__ void cp_wait() {
    asm volatile("cp.async.wait_group %0;" :: "n"(N) : "memory");
}
__device__ __forceinline__ void mma_f16(float& d0, float& d1, float& d2, float& d3,
                                        uint32_t a0, uint32_t a1, uint32_t a2, uint32_t a3,
                                        uint32_t b0, uint32_t b1) {
    asm volatile("mma.sync.aligned.m16n8k16.row.col.f32.f16.f16.f32 "
        "{%0,%1,%2,%3}, {%4,%5,%6,%7}, {%8,%9}, {%0,%1,%2,%3};"
        : "+f"(d0), "+f"(d1), "+f"(d2), "+f"(d3)
        : "r"(a0), "r"(a1), "r"(a2), "r"(a3), "r"(b0), "r"(b1));
}

// ---------------- prep: half weights; W0 channel-permuted ----------------
__global__ void prep_kernel(const float* __restrict__ W0,
                            const float* __restrict__ W1,
                            const float* __restrict__ W2) {
    int tid = blockIdx.x*blockDim.x + threadIdx.x;
    int stride = gridDim.x*blockDim.x;
    for (int i = tid; i < 128*KC0; i += stride) {
        int n = i / KC0, k = i % KC0;
        int src = (k < 64) ? 3 + k : (k < 128) ? 67 + (k - 64) : (k < 131) ? (k - 128) : -1;
        g_w0h[i] = (src >= 0) ? __float2half_rn(W0[n*C_IN + src]) : __float2half_rn(0.f);
    }
    for (int i = tid; i < 128*128; i += stride) {
        g_w1h[i] = __float2half_rn(W1[i]);
        g_w2h[i] = __float2half_rn(W2[i]);
    }
    for (int i = tid; i < 6*128; i += stride) g_stats[i] = 0.f;
}

// ---------------- tiled transpose: f{1,2}[b][c][n] f32 -> f{1,2}t[b][n][c] half ----------------
__global__ void transpose_kernel(const float* __restrict__ f1,
                                 const float* __restrict__ f2) {
    __shared__ float t1[64][33], t2[64][33];
    int b  = blockIdx.y;
    int n0 = blockIdx.x * 32;
    int tid = threadIdx.x;             // 256
    int cr = tid >> 5, nl = tid & 31;
    for (int c = cr; c < 64; c += 8) {
        t1[c][nl] = f1[((size_t)b*64 + c)*NN + n0 + nl];
        t2[c][nl] = f2[((size_t)b*64 + c)*NN + n0 + nl];
    }
    __syncthreads();
    int nw = tid >> 3, cg = (tid & 7) * 8;
    __half2 h[4];
#pragma unroll
    for (int e = 0; e < 4; e++) h[e] = __floats2half2_rn(t1[cg+2*e][nw], t1[cg+2*e+1][nw]);
    *(uint4*)(g_f1t + ((size_t)b*NN + n0 + nw)*64 + cg) = *(uint4*)h;
#pragma unroll
    for (int e = 0; e < 4; e++) h[e] = __floats2half2_rn(t2[cg+2*e][nw], t2[cg+2*e+1][nw]);
    *(uint4*)(g_f2t + ((size_t)b*NN + n0 + nw)*64 + cg) = *(uint4*)h;
}

// ---------------- KNN: 4 threads/query, all candidates in smem, in-block merge ----------------
// block = 128 threads = 32 queries x 4 parts; grid = NQ/32 = 1024
__global__ __launch_bounds__(128) void knn_kernel(const float* __restrict__ p1,
                                                  const float* __restrict__ p2) {
    __shared__ float sx[4096], sy[4096], sz[4096];   // 48KB: full candidate set
    const int tid = threadIdx.x;
    const int q   = blockIdx.x*32 + (tid >> 2);
    const int tg  = tid & 3;
    const int b   = q >> 12;
    const int n   = q & (NN - 1);

    // stage candidates (coalesced)
    for (int i = tid; i < NN; i += 128) {
        sx[i] = p2[(b*3+0)*NN + i];
        sy[i] = p2[(b*3+1)*NN + i];
        sz[i] = p2[(b*3+2)*NN + i];
    }
    const float qx = p1[(b*3+0)*NN + n];
    const float qy = p1[(b*3+1)*NN + n];
    const float qz = p1[(b*3+2)*NN + n];
    __syncthreads();

    float dd[KK]; int ii[KK];
#pragma unroll
    for (int s = 0; s < KK; s++) { dd[s] = 3.4e38f; ii[s] = 0; }
    float worstd = 3.4e38f; int worsts = 0;

    const int t0 = tg * 1024;
    for (int j = 0; j < 1024; j++) {
        int jg = t0 + j;
        float dx = sx[jg]-qx, dy = sy[jg]-qy, dz = sz[jg]-qz;
        float d = fmaf(dx, dx, fmaf(dy, dy, dz*dz));
        if (d < worstd) {
#pragma unroll
            for (int s = 0; s < KK; s++) if (s == worsts) { dd[s] = d; ii[s] = jg; }
            worstd = dd[0]; worsts = 0;
#pragma unroll
            for (int s = 1; s < KK; s++) if (dd[s] > worstd) { worstd = dd[s]; worsts = s; }
        }
    }

    // in-block merge via smem-staged lists (reuse sx for d, sy as int for idx)
    __syncthreads();                     // scanning done; safe to reuse buffers
    float* md = sx;                      // md[tid*16 + s]
    int*   mi = (int*)sy;
#pragma unroll 1
    for (int stage = 1; stage <= 2; stage <<= 1) {
#pragma unroll
        for (int s = 0; s < KK; s++) { md[tid*16 + s] = dd[s]; mi[tid*16 + s] = ii[s]; }
        __syncwarp();
        int partner = tid ^ stage;
#pragma unroll 1
        for (int s = 0; s < KK; s++) {
            float rd = md[partner*16 + s];
            if (rd < worstd) {
                int ri = mi[partner*16 + s];
#pragma unroll
                for (int s2 = 0; s2 < KK; s2++) if (s2 == worsts) { dd[s2] = rd; ii[s2] = ri; }
                worstd = dd[0]; worsts = 0;
#pragma unroll
                for (int s2 = 1; s2 < KK; s2++) if (dd[s2] > worstd) { worstd = dd[s2]; worsts = s2; }
            }
        }
        __syncwarp();
    }
    if (tg == 0) {
#pragma unroll
        for (int s = 0; s < KK; s++) g_idx[q*KK + s] = ii[s];
    }
}

// ---------------- fp16 HMMA GEMM, 256 thr, 128 pos x 128 ch, 2-deep W pipeline ----------------
// MODE 0: X from transposed half tables (vector loads) + xyz scalar chunk
// MODE 1: BN+ReLU on pair-interleaved half X, store half Y
// MODE 2: like 1, but epilogue computes K-group max -> ymax (no Y store)
template<int KC, int MODE>
__global__ __launch_bounds__(256, 2) void gemm_mma(
    const __half* __restrict__ Xp, const __half* __restrict__ Wk,
    const float* __restrict__ bias, const float* __restrict__ sst_in,
    const float* __restrict__ p1g, const float* __restrict__ p2g,
    __half* __restrict__ Yout, float* __restrict__ ymax, float* __restrict__ stats)
{
    extern __shared__ char sm[];
    float* s_bias = (float*)(sm + SC_BIAS);
    float* s_sst  = (float*)(sm + SC_SST);
    float* s_red  = (float*)(sm + SC_RED);

    const int tid = threadIdx.x;
    const int wid = tid >> 5;
    const int lid = tid & 31;
    const int g   = lid >> 2;
    const int tg  = lid & 3;
    const int pos0 = blockIdx.x * 128;
    const int b  = pos0 >> 16;
    const int b3 = b*3;

    const int warp_m = (wid & 1) * 64;
    const int warp_n = (wid >> 1) * 32;

    const int lp   = tid & 127;
    const int hsel = tid >> 7;
    const int lk   = hsel * 16;
    const int kb2  = hsel * 8;
    const int swz  = (lp >> 3) & 3;

    if (tid < 128) s_bias[tid] = bias[tid];
    if (MODE != 0) s_sst[tid] = sst_in[tid];
    s_red[tid] = 0.f;
    __syncthreads();

    const int jidx = (MODE == 0) ? g_idx[pos0 + lp] : 0;
    const int n_p  = ((pos0 + lp) >> 4) & (NN - 1);

    constexpr int NCH = KC / 32;
    const uint32_t smbase = smem_u32(sm);
    const uint32_t* Xw = (const uint32_t*)Xp;

    uint32_t xr32[8];   // half2 words

    auto issueW = [&](int cc) {
        uint32_t wb = smbase + WBUF(cc % 3);
        const char* ws = (const char*)Wk + cc*64;
#pragma unroll
        for (int i = 0; i < 2; i++) {
            int q = tid + i*256;
            int n = q >> 2, jb = q & 3;
            cp16(wb + (uint32_t)(n*80 + jb*16), ws + (size_t)n*(KC*2) + jb*16);
        }
    };
    auto loadXr = [&](int cc) {
        if (MODE == 0) {
            if (cc < 4) {
                const __half* base = (cc < 2) ? g_f2t : g_f1t;
                int row = (cc < 2) ? jidx : n_p;
                int coff = (cc & 1)*32 + lk;
                const uint4* p = (const uint4*)(base + ((size_t)b*NN + row)*64 + coff);
                uint4 v0 = p[0], v1 = p[1];
                xr32[0]=v0.x; xr32[1]=v0.y; xr32[2]=v0.z; xr32[3]=v0.w;
                xr32[4]=v1.x; xr32[5]=v1.y; xr32[6]=v1.z; xr32[7]=v1.w;
            } else {
#pragma unroll
                for (int i = 0; i < 8; i++) xr32[i] = 0u;
                if (hsel == 0) {
                    float x0 = p2g[(b3+0)*NN + jidx] - p1g[(b3+0)*NN + n_p];
                    float x1 = p2g[(b3+1)*NN + jidx] - p1g[(b3+1)*NN + n_p];
                    float x2 = p2g[(b3+2)*NN + jidx] - p1g[(b3+2)*NN + n_p];
                    __half2 h0 = __floats2half2_rn(x0, x1);
                    __half2 h1 = __floats2half2_rn(x2, 0.f);
                    xr32[0] = *(uint32_t*)&h0;
                    xr32[1] = *(uint32_t*)&h1;
                }
            }
        } else {
            int cbase = cc*16 + kb2;
#pragma unroll
            for (int i = 0; i < 8; i++)
                xr32[i] = Xw[(size_t)(cbase + i)*PP + pos0 + lp];
        }
    };
    auto storeXr = [&](int cc) {
        uint32_t* Xb = (uint32_t*)(sm + XBUF(cc % 3));
        if (MODE == 0) {
#pragma unroll
            for (int i = 0; i < 8; i++)
                Xb[lp*20 + ((kb2 + i) ^ swz)] = xr32[i];
        } else {
            int cbase = cc*16 + kb2;
#pragma unroll
            for (int i = 0; i < 8; i++) {
                __half2 h = *(__half2*)&xr32[i];
                int ch2 = 2*(cbase + i);
                float f0 = __low2float(h), f1 = __high2float(h);
                f0 = fmaxf(fmaf(f0, s_sst[ch2],   s_sst[128+ch2]),   0.f);
                f1 = fmaxf(fmaf(f1, s_sst[ch2+1], s_sst[128+ch2+1]), 0.f);
                __half2 o = __floats2half2_rn(f0, f1);
                Xb[lp*20 + ((kb2 + i) ^ swz)] = *(uint32_t*)&o;
            }
        }
    };

    // prologue: W chunks 0,1 in flight; X chunk0 in regs
    issueW(0); cp_commit();
    if (NCH > 1) { issueW(1); cp_commit(); }
    loadXr(0);

    float acc[4][4][4];
#pragma unroll
    for (int mt = 0; mt < 4; mt++)
#pragma unroll
        for (int nt = 0; nt < 4; nt++)
#pragma unroll
            for (int e = 0; e < 4; e++) acc[mt][nt][e] = 0.f;

#pragma unroll 1
    for (int ch = 0; ch < NCH; ch++) {
        storeXr(ch);
        if (ch + 1 < NCH) loadXr(ch + 1);      // global-only; safe pre-barrier
        if (ch == NCH - 1) cp_wait<0>(); else cp_wait<1>();
        __syncthreads();
        if (ch + 2 < NCH) { issueW(ch + 2); cp_commit(); }

        const uint32_t* Xr = (const uint32_t*)(sm + XBUF(ch % 3));
        const uint32_t* Wr = (const uint32_t*)(sm + WBUF(ch % 3));
#pragma unroll
        for (int ks = 0; ks < 2; ks++) {
            uint32_t a[4][4], bb[4][2];
#pragma unroll
            for (int mt = 0; mt < 4; mt++) {
                int row0 = warp_m + mt*16 + g, row1 = row0 + 8;
                int c0 = (2*mt) & 3, c1 = (2*mt + 1) & 3;
                int j0 = 8*ks + (tg ^ c0), j1 = 8*ks + (tg ^ c1);
                a[mt][0] = Xr[row0*20 + j0];
                a[mt][1] = Xr[row1*20 + j1];
                a[mt][2] = Xr[row0*20 + j0 + 4];
                a[mt][3] = Xr[row1*20 + j1 + 4];
            }
#pragma unroll
            for (int nt = 0; nt < 4; nt++) {
                int n = warp_n + nt*8 + g;
                bb[nt][0] = Wr[n*20 + 8*ks + tg];
                bb[nt][1] = Wr[n*20 + 8*ks + tg + 4];
            }
#pragma unroll
            for (int mt = 0; mt < 4; mt++)
#pragma unroll
                for (int nt = 0; nt < 4; nt++)
                    mma_f16(acc[mt][nt][0], acc[mt][nt][1], acc[mt][nt][2], acc[mt][nt][3],
                            a[mt][0], a[mt][1], a[mt][2], a[mt][3],
                            bb[nt][0], bb[nt][1]);
        }
    }

    // ---------- epilogue ----------
    uint32_t* Yw = (uint32_t*)Yout;
    float sp[4][2], qp[4][2];
#pragma unroll
    for (int nt = 0; nt < 4; nt++)
#pragma unroll
        for (int e = 0; e < 2; e++) { sp[nt][e] = 0.f; qp[nt][e] = 0.f; }

#pragma unroll
    for (int mt = 0; mt < 4; mt++) {
        int m = warp_m + mt*16 + g;
        int grp = blockIdx.x*8 + (warp_m >> 4) + mt;
#pragma unroll
        for (int nt = 0; nt < 4; nt++) {
            int ch0 = warp_n + nt*8 + tg*2;
            float bv0 = s_bias[ch0], bv1 = s_bias[ch0+1];
            float v0 = acc[mt][nt][0] + bv0;
            float v1 = acc[mt][nt][1] + bv1;
            float v2 = acc[mt][nt][2] + bv0;
            float v3 = acc[mt][nt][3] + bv1;
            sp[nt][0] += v0 + v2;  qp[nt][0] += fmaf(v0, v0, v2*v2);
            sp[nt][1] += v1 + v3;  qp[nt][1] += fmaf(v1, v1, v3*v3);
            if (MODE == 2) {
                float g0 = fmaxf(v0, v2);
                float g1 = fmaxf(v1, v3);
#pragma unroll
                for (int off = 4; off <= 16; off <<= 1) {
                    g0 = fmaxf(g0, __shfl_xor_sync(0xffffffffu, g0, off));
                    g1 = fmaxf(g1, __shfl_xor_sync(0xffffffffu, g1, off));
                }
                if (g == 0) {
                    ymax[(size_t)ch0*NG + grp]     = g0;
                    ymax[(size_t)(ch0+1)*NG + grp] = g1;
                }
            } else {
                __half2 ha = __floats2half2_rn(v0, v1);
                __half2 hb = __floats2half2_rn(v2, v3);
                uint32_t* yrow = Yw + (size_t)(ch0 >> 1)*PP + pos0;
                yrow[m]     = *(uint32_t*)&ha;
                yrow[m + 8] = *(uint32_t*)&hb;
            }
        }
    }
#pragma unroll
    for (int off = 4; off <= 16; off <<= 1) {
#pragma unroll
        for (int nt = 0; nt < 4; nt++)
#pragma unroll
            for (int e = 0; e < 2; e++) {
                sp[nt][e] += __shfl_xor_sync(0xffffffffu, sp[nt][e], off);
                qp[nt][e] += __shfl_xor_sync(0xffffffffu, qp[nt][e], off);
            }
    }
    if (g == 0) {
#pragma unroll
        for (int nt = 0; nt < 4; nt++)
#pragma unroll
            for (int e = 0; e < 2; e++) {
                int chn = warp_n + nt*8 + tg*2 + e;
                atomicAdd(&s_red[chn], sp[nt][e]);
                atomicAdd(&s_red[128 + chn], qp[nt][e]);
            }
    }
    __syncthreads();
    atomicAdd(&stats[tid], s_red[tid]);
}

// ---------------- BN finalize ----------------
__global__ void finalize_kernel(const float* __restrict__ stats,
                                const float* __restrict__ gamma,
                                const float* __restrict__ beta,
                                float* __restrict__ sst) {
    int chn = threadIdx.x;
    const float inv = 1.0f / (float)PP;
    float mean = stats[chn] * inv;
    float var  = stats[128 + chn] * inv - mean*mean;
    float s = gamma[chn] * rsqrtf(var + BN_EPS);
    sst[chn]       = s;
    sst[128 + chn] = fmaf(-mean, s, beta[chn]);
}

// ---------------- final: BN+ReLU on group maxes ----------------
__global__ void final_out_kernel(const float* __restrict__ ymax,
                                 const float* __restrict__ sst,
                                 float* __restrict__ out) {
    int gid = blockIdx.x*256 + threadIdx.x;   // 128 * NG
    int o = gid >> 15;
    int r = gid & (NG - 1);
    int b = r >> 12, n = r & (NN - 1);
    float v = ymax[gid];
    out[(((size_t)b*128 + o) << 12) + n] = fmaxf(fmaf(v, sst[o], sst[128 + o]), 0.f);
}

// ---------------- launch ----------------
extern "C" void kernel_launch(void* const* d_in, const int* in_sizes, int n_in,
                              void* d_out, int out_size) {
    const float* p1  = (const float*)d_in[0];
    const float* p2  = (const float*)d_in[1];
    const float* f1  = (const float*)d_in[2];
    const float* f2  = (const float*)d_in[3];
    const float* W0  = (const float*)d_in[4];
    const float* b0  = (const float*)d_in[5];
    const float* g0  = (const float*)d_in[6];
    const float* be0 = (const float*)d_in[7];
    const float* W1  = (const float*)d_in[8];
    const float* b1  = (const float*)d_in[9];
    const float* g1  = (const float*)d_in[10];
    const float* be1 = (const float*)d_in[11];
    const float* W2  = (const float*)d_in[12];
    const float* b2  = (const float*)d_in[13];
    const float* g2  = (const float*)d_in[14];
    const float* be2 = (const float*)d_in[15];
    float* out = (float*)d_out;

    static float *stats = nullptr, *sst, *ymax;
    static __half *y0h, *y1h, *w0h, *w1h, *w2h;
    if (!stats) {
        cudaGetSymbolAddress((void**)&stats, g_stats);
        cudaGetSymbolAddress((void**)&sst,   g_sst);
        cudaGetSymbolAddress((void**)&ymax,  g_ymax);
        cudaGetSymbolAddress((void**)&y0h,   g_y0h);
        cudaGetSymbolAddress((void**)&y1h,   g_y1h);
        cudaGetSymbolAddress((void**)&w0h,   g_w0h);
        cudaGetSymbolAddress((void**)&w1h,   g_w1h);
        cudaGetSymbolAddress((void**)&w2h,   g_w2h);
        cudaFuncSetAttribute(gemm_mma<KC0,0>, cudaFuncAttributeMaxDynamicSharedMemorySize, SMEM_BYTES);
        cudaFuncSetAttribute(gemm_mma<128,1>, cudaFuncAttributeMaxDynamicSharedMemorySize, SMEM_BYTES);
        cudaFuncSetAttribute(gemm_mma<128,2>, cudaFuncAttributeMaxDynamicSharedMemorySize, SMEM_BYTES);
    }

    prep_kernel<<<64, 256>>>(W0, W1, W2);                              // 0
    knn_kernel<<<NQ/32, 128>>>(p1, p2);                                // 1
    transpose_kernel<<<dim3(NN/32, BB), 256>>>(f1, f2);                // 2

    // 3 (ncu-profiled): gemm0 with vectorized gather
    gemm_mma<KC0, 0><<<PP/128, 256, SMEM_BYTES>>>(nullptr, w0h, b0, nullptr,
                                     p1, p2, y0h, nullptr, stats + 0*256);
    finalize_kernel<<<1, 128>>>(stats + 0*256, g0, be0, sst + 0*256);

    gemm_mma<128, 1><<<PP/128, 256, SMEM_BYTES>>>(y0h, w1h, b1, sst + 0*256,
                                     nullptr, nullptr, y1h, nullptr, stats + 1*256);
    finalize_kernel<<<1, 128>>>(stats + 1*256, g1, be1, sst + 1*256);

    // gemm2: K-group max fused into epilogue
    gemm_mma<128, 2><<<PP/128, 256, SMEM_BYTES>>>(y1h, w2h, b2, sst + 1*256,
                                     nullptr, nullptr, nullptr, ymax, stats + 2*256);
    finalize_kernel<<<1, 128>>>(stats + 2*256, g2, be2, sst + 2*256);

    final_out_kernel<<<(128*NG)/256, 256>>>(ymax, sst + 2*256, out);
}

// round 16
// speedup vs baseline: 1.1910x; 1.1910x over previous
#include <cuda_runtime.h>
#include <cuda_fp16.h>
#include <math.h>
#include <stdint.h>

#define BB 8
#define NN 4096
#define KK 16
#define CC 64
#define PP (BB*NN*KK)        // 524288 positions
#define NG (PP/16)           // 32768 k-groups
#define NQ 32768             // queries (B*N)
#define C_IN 131
#define KC0 160
#define BN_EPS 1e-3f

// dynamic smem (bytes): 3 X bufs + 3 W bufs (128 rows x 80B) + scalars
#define XBUF(s) ((s)*10240)
#define WBUF(s) (30720 + (s)*10240)
#define SC_BIAS 61440
#define SC_SST  61952
#define SC_RED  62976
#define SMEM_BYTES 64000

// ---------------- scratch ----------------
__device__ int    g_idx[PP];
__device__ __align__(16) __half g_y0h[(size_t)64 * PP * 2];  // pair-interleaved [c2][pos]{2}
__device__ __align__(16) __half g_y1h[(size_t)64 * PP * 2];
__device__ float  g_ymax[(size_t)128 * NG];                  // 16MB
__device__ float  g_stats[6*128];
__device__ __align__(16) __half g_w0h[128*KC0];              // [n][k] permuted: [f2|f1|xyz|pad]
__device__ __align__(16) __half g_w1h[128*128];
__device__ __align__(16) __half g_w2h[128*128];
__device__ __align__(16) __half g_f2t[(size_t)BB*NN*64];     // [b][n][c] half, 4MB
__device__ __align__(16) __half g_f1t[(size_t)BB*NN*64];

__device__ __forceinline__ uint32_t smem_u32(const void* p) {
    uint32_t a;
    asm("{ .reg .u64 t; cvta.to.shared.u64 t, %1; cvt.u32.u64 %0, t; }" : "=r"(a) : "l"(p));
    return a;
}
__device__ __forceinline__ void cp16(uint32_t dst, const void* src) {
    asm volatile("cp.async.ca.shared.global [%0], [%1], 16;" :: "r"(dst), "l"(src));
}
__device__ __forceinline__ void cp_commit() { asm volatile("cp.async.commit_group;"); }
template<int N> __device__ __forceinline__ void cp_wait() {
    asm volatile("cp.async.wait_group %0;" :: "n"(N) : "memory");
}
__device__ __forceinline__ void mma_f16(float& d0, float& d1, float& d2, float& d3,
                                        uint32_t a0, uint32_t a1, uint32_t a2, uint32_t a3,
                                        uint32_t b0, uint32_t b1) {
    asm volatile("mma.sync.aligned.m16n8k16.row.col.f32.f16.f16.f32 "
        "{%0,%1,%2,%3}, {%4,%5,%6,%7}, {%8,%9}, {%0,%1,%2,%3};"
        : "+f"(d0), "+f"(d1), "+f"(d2), "+f"(d3)
        : "r"(a0), "r"(a1), "r"(a2), "r"(a3), "r"(b0), "r"(b1));
}

// ---------------- prep: feature transpose (blocks 0..1023) + half weights (1024..1087) ----------------
__global__ void prep_kernel(const float* __restrict__ W0,
                            const float* __restrict__ W1,
                            const float* __restrict__ W2,
                            const float* __restrict__ f1,
                            const float* __restrict__ f2) {
    if (blockIdx.x < 1024) {
        __shared__ float t1[64][33], t2[64][33];
        int b  = blockIdx.x >> 7;
        int n0 = (blockIdx.x & 127) * 32;
        int tid = threadIdx.x;
        int cr = tid >> 5, nl = tid & 31;
        for (int c = cr; c < 64; c += 8) {
            t1[c][nl] = f1[((size_t)b*64 + c)*NN + n0 + nl];
            t2[c][nl] = f2[((size_t)b*64 + c)*NN + n0 + nl];
        }
        __syncthreads();
        int nw = tid >> 3, cg = (tid & 7) * 8;
        __half2 h[4];
#pragma unroll
        for (int e = 0; e < 4; e++) h[e] = __floats2half2_rn(t1[cg+2*e][nw], t1[cg+2*e+1][nw]);
        *(uint4*)(g_f1t + ((size_t)b*NN + n0 + nw)*64 + cg) = *(uint4*)h;
#pragma unroll
        for (int e = 0; e < 4; e++) h[e] = __floats2half2_rn(t2[cg+2*e][nw], t2[cg+2*e+1][nw]);
        *(uint4*)(g_f2t + ((size_t)b*NN + n0 + nw)*64 + cg) = *(uint4*)h;
    } else {
        int tid = (blockIdx.x - 1024)*blockDim.x + threadIdx.x;
        int stride = 64*blockDim.x;
        for (int i = tid; i < 128*KC0; i += stride) {
            int n = i / KC0, k = i % KC0;
            int src = (k < 64) ? 3 + k : (k < 128) ? 67 + (k - 64) : (k < 131) ? (k - 128) : -1;
            g_w0h[i] = (src >= 0) ? __float2half_rn(W0[n*C_IN + src]) : __float2half_rn(0.f);
        }
        for (int i = tid; i < 128*128; i += stride) {
            g_w1h[i] = __float2half_rn(W1[i]);
            g_w2h[i] = __float2half_rn(W2[i]);
        }
        for (int i = tid; i < 6*128; i += stride) g_stats[i] = 0.f;
    }
}

// ---------------- KNN (R12 monolithic; top-16 via max-replacement) ----------------
__global__ void knn_kernel(const float* __restrict__ p1, const float* __restrict__ p2) {
    const int tid = threadIdx.x;
    const int b = blockIdx.x / (NN/128);
    const int n = (blockIdx.x % (NN/128)) * 128 + tid;

    const float qx = p1[(b*3+0)*NN + n];
    const float qy = p1[(b*3+1)*NN + n];
    const float qz = p1[(b*3+2)*NN + n];

    __shared__ float sx[1024], sy[1024], sz[1024];

    float dd[KK]; int ii[KK];
#pragma unroll
    for (int s = 0; s < KK; s++) { dd[s] = 3.4e38f; ii[s] = 0; }
    float worstd = 3.4e38f; int worsts = 0;

    for (int t0 = 0; t0 < NN; t0 += 1024) {
        __syncthreads();
        for (int i = tid; i < 1024; i += 128) {
            sx[i] = p2[(b*3+0)*NN + t0 + i];
            sy[i] = p2[(b*3+1)*NN + t0 + i];
            sz[i] = p2[(b*3+2)*NN + t0 + i];
        }
        __syncthreads();
        for (int j = 0; j < 1024; j++) {
            float dx = sx[j]-qx, dy = sy[j]-qy, dz = sz[j]-qz;
            float d = fmaf(dx, dx, fmaf(dy, dy, dz*dz));
            if (d < worstd) {
                int jg = t0 + j;
#pragma unroll
                for (int s = 0; s < KK; s++) if (s == worsts) { dd[s] = d; ii[s] = jg; }
                worstd = dd[0]; worsts = 0;
#pragma unroll
                for (int s = 1; s < KK; s++) if (dd[s] > worstd) { worstd = dd[s]; worsts = s; }
            }
        }
    }
#pragma unroll
    for (int s = 0; s < KK; s++) g_idx[(b*NN + n)*KK + s] = ii[s];
}

// ---------------- fp16 HMMA GEMM, 256 thr, 128 pos x 128 ch, 2-deep W pipeline ----------------
// MODE 0: X from transposed half tables (vector loads) + xyz scalar chunk
// MODE 1: BN+ReLU on pair-interleaved half X (scale/shift computed in-block from stats), store half Y
// MODE 2: like 1, but epilogue computes K-group max -> ymax (no Y store)
template<int KC, int MODE>
__global__ __launch_bounds__(256, 2) void gemm_mma(
    const __half* __restrict__ Xp, const __half* __restrict__ Wk,
    const float* __restrict__ bias,
    const float* __restrict__ pstats, const float* __restrict__ gamma,
    const float* __restrict__ beta,
    const float* __restrict__ p1g, const float* __restrict__ p2g,
    __half* __restrict__ Yout, float* __restrict__ ymax, float* __restrict__ stats)
{
    extern __shared__ char sm[];
    float* s_bias = (float*)(sm + SC_BIAS);
    float* s_sst  = (float*)(sm + SC_SST);
    float* s_red  = (float*)(sm + SC_RED);

    const int tid = threadIdx.x;
    const int wid = tid >> 5;
    const int lid = tid & 31;
    const int g   = lid >> 2;
    const int tg  = lid & 3;
    const int pos0 = blockIdx.x * 128;
    const int b  = pos0 >> 16;
    const int b3 = b*3;

    const int warp_m = (wid & 1) * 64;
    const int warp_n = (wid >> 1) * 32;

    const int lp   = tid & 127;
    const int hsel = tid >> 7;
    const int lk   = hsel * 16;
    const int kb2  = hsel * 8;
    const int swz  = (lp >> 3) & 3;

    if (tid < 128) s_bias[tid] = bias[tid];
    if (MODE != 0 && tid < 128) {
        // in-block BN finalize for previous layer
        const float inv = 1.0f / (float)PP;
        float mean = pstats[tid] * inv;
        float var  = pstats[128 + tid] * inv - mean*mean;
        float s = gamma[tid] * rsqrtf(var + BN_EPS);
        s_sst[tid]       = s;
        s_sst[128 + tid] = fmaf(-mean, s, beta[tid]);
    }
    s_red[tid] = 0.f;
    __syncthreads();

    const int jidx = (MODE == 0) ? g_idx[pos0 + lp] : 0;
    const int n_p  = ((pos0 + lp) >> 4) & (NN - 1);

    constexpr int NCH = KC / 32;
    const uint32_t smbase = smem_u32(sm);
    const uint32_t* Xw = (const uint32_t*)Xp;

    uint32_t xr32[8];   // half2 words

    auto issueW = [&](int cc) {
        uint32_t wb = smbase + WBUF(cc % 3);
        const char* ws = (const char*)Wk + cc*64;
#pragma unroll
        for (int i = 0; i < 2; i++) {
            int q = tid + i*256;
            int n = q >> 2, jb = q & 3;
            cp16(wb + (uint32_t)(n*80 + jb*16), ws + (size_t)n*(KC*2) + jb*16);
        }
    };
    auto loadXr = [&](int cc) {
        if (MODE == 0) {
            if (cc < 4) {
                const __half* base = (cc < 2) ? g_f2t : g_f1t;
                int row = (cc < 2) ? jidx : n_p;
                int coff = (cc & 1)*32 + lk;
                const uint4* p = (const uint4*)(base + ((size_t)b*NN + row)*64 + coff);
                uint4 v0 = p[0], v1 = p[1];
                xr32[0]=v0.x; xr32[1]=v0.y; xr32[2]=v0.z; xr32[3]=v0.w;
                xr32[4]=v1.x; xr32[5]=v1.y; xr32[6]=v1.z; xr32[7]=v1.w;
            } else {
#pragma unroll
                for (int i = 0; i < 8; i++) xr32[i] = 0u;
                if (hsel == 0) {
                    float x0 = p2g[(b3+0)*NN + jidx] - p1g[(b3+0)*NN + n_p];
                    float x1 = p2g[(b3+1)*NN + jidx] - p1g[(b3+1)*NN + n_p];
                    float x2 = p2g[(b3+2)*NN + jidx] - p1g[(b3+2)*NN + n_p];
                    __half2 h0 = __floats2half2_rn(x0, x1);
                    __half2 h1 = __floats2half2_rn(x2, 0.f);
                    xr32[0] = *(uint32_t*)&h0;
                    xr32[1] = *(uint32_t*)&h1;
                }
            }
        } else {
            int cbase = cc*16 + kb2;
#pragma unroll
            for (int i = 0; i < 8; i++)
                xr32[i] = Xw[(size_t)(cbase + i)*PP + pos0 + lp];
        }
    };
    auto storeXr = [&](int cc) {
        uint32_t* Xb = (uint32_t*)(sm + XBUF(cc % 3));
        if (MODE == 0) {
#pragma unroll
            for (int i = 0; i < 8; i++)
                Xb[lp*20 + ((kb2 + i) ^ swz)] = xr32[i];
        } else {
            int cbase = cc*16 + kb2;
#pragma unroll
            for (int i = 0; i < 8; i++) {
                __half2 h = *(__half2*)&xr32[i];
                int ch2 = 2*(cbase + i);
                float f0 = __low2float(h), f1 = __high2float(h);
                f0 = fmaxf(fmaf(f0, s_sst[ch2],   s_sst[128+ch2]),   0.f);
                f1 = fmaxf(fmaf(f1, s_sst[ch2+1], s_sst[128+ch2+1]), 0.f);
                __half2 o = __floats2half2_rn(f0, f1);
                Xb[lp*20 + ((kb2 + i) ^ swz)] = *(uint32_t*)&o;
            }
        }
    };

    // prologue: W chunks 0,1 in flight; X chunk0 in regs
    issueW(0); cp_commit();
    if (NCH > 1) { issueW(1); cp_commit(); }
    loadXr(0);

    float acc[4][4][4];
#pragma unroll
    for (int mt = 0; mt < 4; mt++)
#pragma unroll
        for (int nt = 0; nt < 4; nt++)
#pragma unroll
            for (int e = 0; e < 4; e++) acc[mt][nt][e] = 0.f;

#pragma unroll 1
    for (int ch = 0; ch < NCH; ch++) {
        storeXr(ch);
        if (ch + 1 < NCH) loadXr(ch + 1);      // global-only; safe pre-barrier
        if (ch == NCH - 1) cp_wait<0>(); else cp_wait<1>();
        __syncthreads();
        if (ch + 2 < NCH) { issueW(ch + 2); cp_commit(); }

        const uint32_t* Xr = (const uint32_t*)(sm + XBUF(ch % 3));
        const uint32_t* Wr = (const uint32_t*)(sm + WBUF(ch % 3));
#pragma unroll
        for (int ks = 0; ks < 2; ks++) {
            uint32_t a[4][4], bb[4][2];
#pragma unroll
            for (int mt = 0; mt < 4; mt++) {
                int row0 = warp_m + mt*16 + g, row1 = row0 + 8;
                int c0 = (2*mt) & 3, c1 = (2*mt + 1) & 3;
                int j0 = 8*ks + (tg ^ c0), j1 = 8*ks + (tg ^ c1);
                a[mt][0] = Xr[row0*20 + j0];
                a[mt][1] = Xr[row1*20 + j1];
                a[mt][2] = Xr[row0*20 + j0 + 4];
                a[mt][3] = Xr[row1*20 + j1 + 4];
            }
#pragma unroll
            for (int nt = 0; nt < 4; nt++) {
                int n = warp_n + nt*8 + g;
                bb[nt][0] = Wr[n*20 + 8*ks + tg];
                bb[nt][1] = Wr[n*20 + 8*ks + tg + 4];
            }
#pragma unroll
            for (int mt = 0; mt < 4; mt++)
#pragma unroll
                for (int nt = 0; nt < 4; nt++)
                    mma_f16(acc[mt][nt][0], acc[mt][nt][1], acc[mt][nt][2], acc[mt][nt][3],
                            a[mt][0], a[mt][1], a[mt][2], a[mt][3],
                            bb[nt][0], bb[nt][1]);
        }
    }

    // ---------- epilogue ----------
    uint32_t* Yw = (uint32_t*)Yout;
    float sp[4][2], qp[4][2];
#pragma unroll
    for (int nt = 0; nt < 4; nt++)
#pragma unroll
        for (int e = 0; e < 2; e++) { sp[nt][e] = 0.f; qp[nt][e] = 0.f; }

#pragma unroll
    for (int mt = 0; mt < 4; mt++) {
        int m = warp_m + mt*16 + g;
        int grp = blockIdx.x*8 + (warp_m >> 4) + mt;
#pragma unroll
        for (int nt = 0; nt < 4; nt++) {
            int ch0 = warp_n + nt*8 + tg*2;
            float bv0 = s_bias[ch0], bv1 = s_bias[ch0+1];
            float v0 = acc[mt][nt][0] + bv0;
            float v1 = acc[mt][nt][1] + bv1;
            float v2 = acc[mt][nt][2] + bv0;
            float v3 = acc[mt][nt][3] + bv1;
            sp[nt][0] += v0 + v2;  qp[nt][0] += fmaf(v0, v0, v2*v2);
            sp[nt][1] += v1 + v3;  qp[nt][1] += fmaf(v1, v1, v3*v3);
            if (MODE == 2) {
                float g0 = fmaxf(v0, v2);
                float g1 = fmaxf(v1, v3);
#pragma unroll
                for (int off = 4; off <= 16; off <<= 1) {
                    g0 = fmaxf(g0, __shfl_xor_sync(0xffffffffu, g0, off));
                    g1 = fmaxf(g1, __shfl_xor_sync(0xffffffffu, g1, off));
                }
                if (g == 0) {
                    ymax[(size_t)ch0*NG + grp]     = g0;
                    ymax[(size_t)(ch0+1)*NG + grp] = g1;
                }
            } else {
                __half2 ha = __floats2half2_rn(v0, v1);
                __half2 hb = __floats2half2_rn(v2, v3);
                uint32_t* yrow = Yw + (size_t)(ch0 >> 1)*PP + pos0;
                yrow[m]     = *(uint32_t*)&ha;
                yrow[m + 8] = *(uint32_t*)&hb;
            }
        }
    }
#pragma unroll
    for (int off = 4; off <= 16; off <<= 1) {
#pragma unroll
        for (int nt = 0; nt < 4; nt++)
#pragma unroll
            for (int e = 0; e < 2; e++) {
                sp[nt][e] += __shfl_xor_sync(0xffffffffu, sp[nt][e], off);
                qp[nt][e] += __shfl_xor_sync(0xffffffffu, qp[nt][e], off);
            }
    }
    if (g == 0) {
#pragma unroll
        for (int nt = 0; nt < 4; nt++)
#pragma unroll
            for (int e = 0; e < 2; e++) {
                int chn = warp_n + nt*8 + tg*2 + e;
                atomicAdd(&s_red[chn], sp[nt][e]);
                atomicAdd(&s_red[128 + chn], qp[nt][e]);
            }
    }
    __syncthreads();
    atomicAdd(&stats[tid], s_red[tid]);
}

// ---------------- final: BN+ReLU on group maxes (in-block finalize of layer-2 stats) ----------------
__global__ void final_out_kernel(const float* __restrict__ ymax,
                                 const float* __restrict__ stats,
                                 const float* __restrict__ gamma,
                                 const float* __restrict__ beta,
                                 float* __restrict__ out) {
    __shared__ float s2[2];
    int gid = blockIdx.x*256 + threadIdx.x;   // 128 * NG; one o per block (NG/256=128 blocks per o)
    int o = gid >> 15;
    if (threadIdx.x == 0) {
        const float inv = 1.0f / (float)PP;
        float mean = stats[o] * inv;
        float var  = stats[128 + o] * inv - mean*mean;
        float s = gamma[o] * rsqrtf(var + BN_EPS);
        s2[0] = s;
        s2[1] = fmaf(-mean, s, beta[o]);
    }
    __syncthreads();
    int r = gid & (NG - 1);
    int b = r >> 12, n = r & (NN - 1);
    float v = ymax[gid];
    out[(((size_t)b*128 + o) << 12) + n] = fmaxf(fmaf(v, s2[0], s2[1]), 0.f);
}

// ---------------- launch ----------------
extern "C" void kernel_launch(void* const* d_in, const int* in_sizes, int n_in,
                              void* d_out, int out_size) {
    const float* p1  = (const float*)d_in[0];
    const float* p2  = (const float*)d_in[1];
    const float* f1  = (const float*)d_in[2];
    const float* f2  = (const float*)d_in[3];
    const float* W0  = (const float*)d_in[4];
    const float* b0  = (const float*)d_in[5];
    const float* g0  = (const float*)d_in[6];
    const float* be0 = (const float*)d_in[7];
    const float* W1  = (const float*)d_in[8];
    const float* b1  = (const float*)d_in[9];
    const float* g1  = (const float*)d_in[10];
    const float* be1 = (const float*)d_in[11];
    const float* W2  = (const float*)d_in[12];
    const float* b2  = (const float*)d_in[13];
    const float* g2  = (const float*)d_in[14];
    const float* be2 = (const float*)d_in[15];
    float* out = (float*)d_out;

    static float *stats = nullptr, *ymax;
    static __half *y0h, *y1h, *w0h, *w1h, *w2h;
    if (!stats) {
        cudaGetSymbolAddress((void**)&stats, g_stats);
        cudaGetSymbolAddress((void**)&ymax,  g_ymax);
        cudaGetSymbolAddress((void**)&y0h,   g_y0h);
        cudaGetSymbolAddress((void**)&y1h,   g_y1h);
        cudaGetSymbolAddress((void**)&w0h,   g_w0h);
        cudaGetSymbolAddress((void**)&w1h,   g_w1h);
        cudaGetSymbolAddress((void**)&w2h,   g_w2h);
        cudaFuncSetAttribute(gemm_mma<KC0,0>, cudaFuncAttributeMaxDynamicSharedMemorySize, SMEM_BYTES);
        cudaFuncSetAttribute(gemm_mma<128,1>, cudaFuncAttributeMaxDynamicSharedMemorySize, SMEM_BYTES);
        cudaFuncSetAttribute(gemm_mma<128,2>, cudaFuncAttributeMaxDynamicSharedMemorySize, SMEM_BYTES);
    }

    prep_kernel<<<1088, 256>>>(W0, W1, W2, f1, f2);                    // 0 (weights + transpose)
    knn_kernel<<<BB*(NN/128), 128>>>(p1, p2);                          // 1

    // 2: gemm0 (inline vectorized gather)
    gemm_mma<KC0, 0><<<PP/128, 256, SMEM_BYTES>>>(nullptr, w0h, b0,
                                     nullptr, nullptr, nullptr,
                                     p1, p2, y0h, nullptr, stats + 0*256);

    // 3 (ncu-profiled): gemm1, BN(layer0)+ReLU fused on load
    gemm_mma<128, 1><<<PP/128, 256, SMEM_BYTES>>>(y0h, w1h, b1,
                                     stats + 0*256, g0, be0,
                                     nullptr, nullptr, y1h, nullptr, stats + 1*256);

    // 4: gemm2, BN(layer1)+ReLU on load, K-group max fused in epilogue
    gemm_mma<128, 2><<<PP/128, 256, SMEM_BYTES>>>(y1h, w2h, b2,
                                     stats + 1*256, g1, be1,
                                     nullptr, nullptr, nullptr, ymax, stats + 2*256);

    // 5: final BN+ReLU on group maxes
    final_out_kernel<<<(128*NG)/256, 256>>>(ymax, stats + 2*256, g2, be2, out);
}